// round 2
// baseline (speedup 1.0000x reference)
#include <cuda_runtime.h>
#include <cuda_bf16.h>
#include <cstdint>

// Problem constants (from reference)
#define NNODES   100000
#define EDIM     256          // IN_DIM == OUT_DIM == 256
#define NEDGES   3200000

// Scratch for h = x@W + b  (100000 x 256 f32 = 102.4 MB). Static __device__
// array per the allocation-guard rules (no cudaMalloc anywhere).
__device__ float g_h[(size_t)NNODES * EDIM];

// Index-dtype flag: 1 if G_rows/G_cols are int64, 0 if int32.
__device__ int g_idx_is_64;

// ---------------------------------------------------------------------------
// Kernel D: detect index dtype. Interpret first K entries as int64; if any is
// out of [0, N) the buffer must really be int32 (an int32 pair (lo,hi) forms
// lo + hi*2^32 which is astronomically unlikely to stay < N for all samples).
// ---------------------------------------------------------------------------
__global__ void detect_idx_dtype_kernel(const long long* __restrict__ rows,
                                        int nelem, int N) {
    int k = nelem < 1024 ? nelem : 1024;
    int is64 = 1;
    for (int i = 0; i < k; i++) {
        long long v = rows[i];           // safe: int32 buffer of E elems holds E/2 int64s; k<<E/2
        if (v < 0 || v >= (long long)N) { is64 = 0; break; }
    }
    g_idx_is_64 = is64;
}

// ---------------------------------------------------------------------------
// Kernel 0: zero the output buffer (harness poisons it with 0xAA).
// ---------------------------------------------------------------------------
__global__ void zero_kernel(float4* __restrict__ out4, int nvec,
                            float* __restrict__ out, int total) {
    int i = blockIdx.x * blockDim.x + threadIdx.x;
    if (i < nvec) out4[i] = make_float4(0.f, 0.f, 0.f, 0.f);
    if (i == 0) {
        for (int j = nvec * 4; j < total; j++) out[j] = 0.f;
    }
}

// ---------------------------------------------------------------------------
// Kernel 1: h = x @ W + bias
// Tiled SGEMM: 64x64 tile, BK=16, 256 threads, 4x4 per thread.
// ---------------------------------------------------------------------------
__global__ __launch_bounds__(256)
void gemm_bias_kernel(const float* __restrict__ X,
                      const float* __restrict__ W,
                      const float* __restrict__ bias,
                      float* __restrict__ H, int N) {
    __shared__ float As[16][64];   // As[k][m]
    __shared__ float Bs[16][64];   // Bs[k][n]

    const int t  = threadIdx.x;
    const int bm = blockIdx.x * 64;
    const int bn = blockIdx.y * 64;
    const int tx = t & 15;
    const int ty = t >> 4;

    float acc[4][4] = {};

    const int a_row = t >> 2;            // 0..63
    const int a_k4  = (t & 3) * 4;       // 0,4,8,12
    const int b_k   = t >> 4;            // 0..15
    const int b_c4  = (t & 15) * 4;      // 0..60

    for (int k0 = 0; k0 < EDIM; k0 += 16) {
        {
            int grow = bm + a_row;
            float4 a = make_float4(0.f, 0.f, 0.f, 0.f);
            if (grow < N)
                a = *(const float4*)(X + (size_t)grow * EDIM + k0 + a_k4);
            As[a_k4 + 0][a_row] = a.x;
            As[a_k4 + 1][a_row] = a.y;
            As[a_k4 + 2][a_row] = a.z;
            As[a_k4 + 3][a_row] = a.w;
        }
        {
            float4 b = *(const float4*)(W + (size_t)(k0 + b_k) * EDIM + bn + b_c4);
            *(float4*)&Bs[b_k][b_c4] = b;
        }
        __syncthreads();

        #pragma unroll
        for (int k = 0; k < 16; k++) {
            float am[4], bb[4];
            #pragma unroll
            for (int i = 0; i < 4; i++) am[i] = As[k][ty * 4 + i];
            #pragma unroll
            for (int j = 0; j < 4; j++) bb[j] = Bs[k][tx * 4 + j];
            #pragma unroll
            for (int i = 0; i < 4; i++)
                #pragma unroll
                for (int j = 0; j < 4; j++)
                    acc[i][j] += am[i] * bb[j];
        }
        __syncthreads();
    }

    float4 bv = *(const float4*)(bias + bn + tx * 4);
    #pragma unroll
    for (int i = 0; i < 4; i++) {
        int grow = bm + ty * 4 + i;
        if (grow < N) {
            float4 o;
            o.x = acc[i][0] + bv.x;
            o.y = acc[i][1] + bv.y;
            o.z = acc[i][2] + bv.z;
            o.w = acc[i][3] + bv.w;
            *(float4*)(H + (size_t)grow * EDIM + bn + tx * 4) = o;
        }
    }
}

// ---------------------------------------------------------------------------
// Kernel 2: out[r] += vals[e] * h[c]   (one warp per edge)
// Lane l owns elements {l + 32j}: every load / atomicAdd instruction covers
// 32 consecutive 4B addresses (coalesced 128B). Index dtype chosen at runtime
// via g_idx_is_64. Indices range-guarded: bad index -> skip, not crash.
// ---------------------------------------------------------------------------
__global__ __launch_bounds__(256)
void spmm_atomic_kernel(const void* __restrict__ rows_raw,
                        const void* __restrict__ cols_raw,
                        const float* __restrict__ vals,
                        const float* __restrict__ H,
                        float* __restrict__ out, int E, int N) {
    long long gid = (long long)blockIdx.x * blockDim.x + threadIdx.x;
    int e    = (int)(gid >> 5);
    int lane = (int)(gid & 31);
    if (e >= E) return;

    long long r, c;
    if (g_idx_is_64) {
        r = __ldg((const long long*)rows_raw + e);
        c = __ldg((const long long*)cols_raw + e);
    } else {
        r = __ldg((const int*)rows_raw + e);
        c = __ldg((const int*)cols_raw + e);
    }
    if ((unsigned long long)r >= (unsigned long long)N ||
        (unsigned long long)c >= (unsigned long long)N) return;

    float v = __ldg(&vals[e]);

    const float* h = H   + (size_t)c * EDIM + lane;
    float*       o = out + (size_t)r * EDIM + lane;

    float g[8];
    #pragma unroll
    for (int j = 0; j < 8; j++) g[j] = __ldg(h + j * 32);
    #pragma unroll
    for (int j = 0; j < 8; j++) atomicAdd(o + j * 32, v * g[j]);
}

// ---------------------------------------------------------------------------
// Launch. Inputs (metadata order): x, G_rows, G_cols, G_vals, weight, bias.
// ---------------------------------------------------------------------------
extern "C" void kernel_launch(void* const* d_in, const int* in_sizes, int n_in,
                              void* d_out, int out_size) {
    const float* x     = (const float*)d_in[0];
    const void*  grows = d_in[1];
    const void*  gcols = d_in[2];
    const float* gvals = (const float*)d_in[3];
    const float* w     = (const float*)d_in[4];
    const float* bias  = (const float*)d_in[5];
    float*       out   = (float*)d_out;

    const int N = in_sizes[0] / EDIM;     // 100000
    const int E = in_sizes[1];            // 3200000

    float* d_h = nullptr;
    cudaGetSymbolAddress((void**)&d_h, g_h);

    // D) detect index dtype (inside graph; deterministic)
    detect_idx_dtype_kernel<<<1, 1>>>((const long long*)grows, E, N);

    // 0) zero output
    {
        int nvec = out_size / 4;
        int blocks = (nvec + 255) / 256;
        zero_kernel<<<blocks, 256>>>((float4*)out, nvec, out, out_size);
    }

    // 1) h = x @ W + bias
    {
        dim3 grid((N + 63) / 64, EDIM / 64);
        gemm_bias_kernel<<<grid, 256>>>(x, w, bias, d_h, N);
    }

    // 2) out[r] += vals * h[c]
    {
        long long threads = (long long)E * 32;
        int blocks = (int)((threads + 255) / 256);
        spmm_atomic_kernel<<<blocks, 256>>>(grows, gcols, gvals, d_h, out, E, N);
    }
}

// round 3
// speedup vs baseline: 1.8190x; 1.8190x over previous
#include <cuda_runtime.h>
#include <cuda_bf16.h>
#include <cstdint>

#define NNODES   100000
#define EDIM     256
#define NEDGES   3200000
#define NB_SCAN  ((NNODES + 1023) / 1024)   // 98 scan blocks

// Static device scratch (no allocations allowed anywhere).
__device__ float g_h[(size_t)NNODES * EDIM];          // 102.4 MB  h = xW+b
__device__ int   g_deg[NNODES];
__device__ int   g_rowptr[NNODES + 1];
__device__ int   g_cursor[NNODES];
__device__ int   g_bsum[1024];
__device__ int2  g_edges[NEDGES];                     // {col, val-bits} CSR payload
__device__ int   g_idx_is_64;

// ---------------------------------------------------------------------------
// detect index dtype: 32 parallel samples interpreted as int64; all in-range
// => really int64. (int32 data: each sample needs hi-word==0, P ~ 1e-145.)
// ---------------------------------------------------------------------------
__global__ void detect_idx_dtype_kernel(const long long* __restrict__ rows,
                                        int nelem, int N) {
    int t = threadIdx.x;                      // 32 threads
    int k = nelem / 4 < 32 ? nelem / 4 : 32;  // stay inside even if int32 buffer
    bool ok = true;
    if (t < k) {
        long long v = rows[t];
        ok = (v >= 0 && v < (long long)N);
    }
    unsigned m = __ballot_sync(0xffffffffu, ok);
    if (t == 0) g_idx_is_64 = (m == 0xffffffffu) ? 1 : 0;
}

// zero int array (degree counters)
__global__ void zero_int_kernel(int* __restrict__ p, int n) {
    int i = blockIdx.x * blockDim.x + threadIdx.x;
    if (i < n) p[i] = 0;
}

// zero tail of output beyond N*EDIM (covers trailing recon scalar)
__global__ void zero_tail_kernel(float* __restrict__ out, int lo, int hi) {
    int i = lo + blockIdx.x * blockDim.x + threadIdx.x;
    if (i < hi) out[i] = 0.f;
}

// ---------------------------------------------------------------------------
// CSR build
// ---------------------------------------------------------------------------
__global__ __launch_bounds__(256)
void hist_kernel(const void* __restrict__ rows_raw, int E, int N,
                 int* __restrict__ deg) {
    int e = blockIdx.x * blockDim.x + threadIdx.x;
    if (e >= E) return;
    int r = g_idx_is_64 ? (int)__ldg((const long long*)rows_raw + e)
                        : __ldg((const int*)rows_raw + e);
    if ((unsigned)r < (unsigned)N) atomicAdd(&deg[r], 1);
}

// block-local exclusive scan; emits per-block totals
__global__ __launch_bounds__(1024)
void scan1_kernel(const int* __restrict__ deg, int* __restrict__ rowptr,
                  int* __restrict__ bsum, int N) {
    __shared__ int s[1024];
    int t = threadIdx.x;
    int i = blockIdx.x * 1024 + t;
    int v = (i < N) ? deg[i] : 0;
    s[t] = v;
    __syncthreads();
    for (int off = 1; off < 1024; off <<= 1) {
        int u = (t >= off) ? s[t - off] : 0;
        __syncthreads();
        s[t] += u;
        __syncthreads();
    }
    if (i < N) rowptr[i] = s[t] - v;          // exclusive within block
    if (t == 1023) bsum[blockIdx.x] = s[1023];
}

// scan the block sums (nb <= 1024), convert to exclusive in place
__global__ __launch_bounds__(1024)
void scan2_kernel(int* __restrict__ bsum, int nb) {
    __shared__ int s[1024];
    int t = threadIdx.x;
    int v = (t < nb) ? bsum[t] : 0;
    s[t] = v;
    __syncthreads();
    for (int off = 1; off < 1024; off <<= 1) {
        int u = (t >= off) ? s[t - off] : 0;
        __syncthreads();
        s[t] += u;
        __syncthreads();
    }
    if (t < nb) bsum[t] = s[t] - v;           // exclusive
}

// add block offsets, init cursors, set rowptr[N]=E
__global__ __launch_bounds__(1024)
void scan3_kernel(int* __restrict__ rowptr, int* __restrict__ cursor,
                  const int* __restrict__ bsum, int N, int E) {
    int i = blockIdx.x * 1024 + threadIdx.x;
    if (i < N) {
        int v = rowptr[i] + bsum[blockIdx.x];
        rowptr[i] = v;
        cursor[i] = v;
    }
    if (i == 0) rowptr[N] = E;
}

__global__ __launch_bounds__(256)
void scatter_kernel(const void* __restrict__ rows_raw,
                    const void* __restrict__ cols_raw,
                    const float* __restrict__ vals,
                    int* __restrict__ cursor,
                    int2* __restrict__ edges, int E, int N) {
    int e = blockIdx.x * blockDim.x + threadIdx.x;
    if (e >= E) return;
    int r, c;
    if (g_idx_is_64) {
        r = (int)__ldg((const long long*)rows_raw + e);
        c = (int)__ldg((const long long*)cols_raw + e);
    } else {
        r = __ldg((const int*)rows_raw + e);
        c = __ldg((const int*)cols_raw + e);
    }
    if ((unsigned)r >= (unsigned)N || (unsigned)c >= (unsigned)N) return;
    float v = __ldg(&vals[e]);
    int pos = atomicAdd(&cursor[r], 1);
    if (pos < NEDGES) edges[pos] = make_int2(c, __float_as_int(v));
}

// ---------------------------------------------------------------------------
// GEMM: h = x @ W + bias   (64x64 tile, BK=16, 256 threads, 4x4/thread)
// ---------------------------------------------------------------------------
__global__ __launch_bounds__(256)
void gemm_bias_kernel(const float* __restrict__ X,
                      const float* __restrict__ W,
                      const float* __restrict__ bias,
                      float* __restrict__ H, int N) {
    __shared__ float As[16][64];
    __shared__ float Bs[16][64];

    const int t  = threadIdx.x;
    const int bm = blockIdx.x * 64;
    const int bn = blockIdx.y * 64;
    const int tx = t & 15;
    const int ty = t >> 4;

    float acc[4][4] = {};

    const int a_row = t >> 2;
    const int a_k4  = (t & 3) * 4;
    const int b_k   = t >> 4;
    const int b_c4  = (t & 15) * 4;

    for (int k0 = 0; k0 < EDIM; k0 += 16) {
        {
            int grow = bm + a_row;
            float4 a = make_float4(0.f, 0.f, 0.f, 0.f);
            if (grow < N)
                a = *(const float4*)(X + (size_t)grow * EDIM + k0 + a_k4);
            As[a_k4 + 0][a_row] = a.x;
            As[a_k4 + 1][a_row] = a.y;
            As[a_k4 + 2][a_row] = a.z;
            As[a_k4 + 3][a_row] = a.w;
        }
        {
            float4 b = *(const float4*)(W + (size_t)(k0 + b_k) * EDIM + bn + b_c4);
            *(float4*)&Bs[b_k][b_c4] = b;
        }
        __syncthreads();

        #pragma unroll
        for (int k = 0; k < 16; k++) {
            float4 am = *(const float4*)&As[k][ty * 4];
            float4 bb = *(const float4*)&Bs[k][tx * 4];
            float a4[4] = {am.x, am.y, am.z, am.w};
            float b4[4] = {bb.x, bb.y, bb.z, bb.w};
            #pragma unroll
            for (int i = 0; i < 4; i++)
                #pragma unroll
                for (int j = 0; j < 4; j++)
                    acc[i][j] += a4[i] * b4[j];
        }
        __syncthreads();
    }

    float4 bv = *(const float4*)(bias + bn + tx * 4);
    #pragma unroll
    for (int i = 0; i < 4; i++) {
        int grow = bm + ty * 4 + i;
        if (grow < N) {
            float4 o;
            o.x = acc[i][0] + bv.x;
            o.y = acc[i][1] + bv.y;
            o.z = acc[i][2] + bv.z;
            o.w = acc[i][3] + bv.w;
            *(float4*)(H + (size_t)grow * EDIM + bn + tx * 4) = o;
        }
    }
}

// ---------------------------------------------------------------------------
// SpMM over CSR: one warp per output row, register accumulation, no atomics.
// Lane l owns float4 chunks at l and l+32 (two coalesced 128B groups).
// ---------------------------------------------------------------------------
__global__ __launch_bounds__(256)
void spmm_csr_kernel(const int* __restrict__ rowptr,
                     const int2* __restrict__ edges,
                     const float* __restrict__ H,
                     float* __restrict__ out, int N) {
    int warp = (blockIdx.x * blockDim.x + threadIdx.x) >> 5;
    int lane = threadIdx.x & 31;
    if (warp >= N) return;

    int s = __ldg(&rowptr[warp]);
    int e = __ldg(&rowptr[warp + 1]);

    float4 a0 = make_float4(0.f, 0.f, 0.f, 0.f);
    float4 a1 = make_float4(0.f, 0.f, 0.f, 0.f);

    #pragma unroll 4
    for (int i = s; i < e; i++) {
        int2  ev = __ldg(&edges[i]);
        float v  = __int_as_float(ev.y);
        const float4* hp = (const float4*)(H + (size_t)ev.x * EDIM);
        float4 x0 = __ldg(hp + lane);
        float4 x1 = __ldg(hp + lane + 32);
        a0.x += v * x0.x;  a0.y += v * x0.y;  a0.z += v * x0.z;  a0.w += v * x0.w;
        a1.x += v * x1.x;  a1.y += v * x1.y;  a1.z += v * x1.z;  a1.w += v * x1.w;
    }

    float4* op = (float4*)(out + (size_t)warp * EDIM);
    op[lane]      = a0;
    op[lane + 32] = a1;
}

// ---------------------------------------------------------------------------
// Launch. Inputs: x, G_rows, G_cols, G_vals, weight, bias.
// ---------------------------------------------------------------------------
extern "C" void kernel_launch(void* const* d_in, const int* in_sizes, int n_in,
                              void* d_out, int out_size) {
    const float* x     = (const float*)d_in[0];
    const void*  grows = d_in[1];
    const void*  gcols = d_in[2];
    const float* gvals = (const float*)d_in[3];
    const float* w     = (const float*)d_in[4];
    const float* bias  = (const float*)d_in[5];
    float*       out   = (float*)d_out;

    const int N = in_sizes[0] / EDIM;     // 100000
    const int E = in_sizes[1];            // 3200000

    float *d_h;    cudaGetSymbolAddress((void**)&d_h, g_h);
    int   *d_deg;  cudaGetSymbolAddress((void**)&d_deg, g_deg);
    int   *d_rp;   cudaGetSymbolAddress((void**)&d_rp, g_rowptr);
    int   *d_cur;  cudaGetSymbolAddress((void**)&d_cur, g_cursor);
    int   *d_bs;   cudaGetSymbolAddress((void**)&d_bs, g_bsum);
    int2  *d_edg;  cudaGetSymbolAddress((void**)&d_edg, g_edges);

    const int nb = (N + 1023) / 1024;

    // dtype probe + zero degree counters + zero output tail
    detect_idx_dtype_kernel<<<1, 32>>>((const long long*)grows, E, N);
    zero_int_kernel<<<(N + 255) / 256, 256>>>(d_deg, N);
    {
        int lo = N * EDIM;
        if (out_size > lo)
            zero_tail_kernel<<<(out_size - lo + 255) / 256, 256>>>(out, lo, out_size);
    }

    // CSR build
    hist_kernel<<<(E + 255) / 256, 256>>>(grows, E, N, d_deg);
    scan1_kernel<<<nb, 1024>>>(d_deg, d_rp, d_bs, N);
    scan2_kernel<<<1, 1024>>>(d_bs, nb);
    scan3_kernel<<<nb, 1024>>>(d_rp, d_cur, d_bs, N, E);
    scatter_kernel<<<(E + 255) / 256, 256>>>(grows, gcols, gvals, d_cur, d_edg, E, N);

    // h = x @ W + bias
    {
        dim3 grid((N + 63) / 64, EDIM / 64);
        gemm_bias_kernel<<<grid, 256>>>(x, w, bias, d_h, N);
    }

    // out = G @ h  (no atomics)
    {
        long long threads = (long long)N * 32;
        int blocks = (int)((threads + 255) / 256);
        spmm_csr_kernel<<<blocks, 256>>>(d_rp, d_edg, d_h, out, N);
    }
}

// round 5
// speedup vs baseline: 2.7486x; 1.5111x over previous
#include <cuda_runtime.h>
#include <cuda_bf16.h>
#include <cstdint>

#define NNODES   100000
#define EDIM     256
#define NEDGES   3200000

// Static device scratch (no allocations allowed anywhere).
__device__ float g_h[(size_t)NNODES * EDIM];          // 102.4 MB  h = xW+b
__device__ int   g_deg[NNODES];
__device__ int   g_rowptr[NNODES + 1];
__device__ int   g_cursor[NNODES];
__device__ int   g_bsum[1024];
__device__ int2  g_edges[NEDGES];                     // {col, val-bits} CSR payload
__device__ int   g_idx_is_64;

// ---------------------------------------------------------------------------
// detect index dtype: 32 parallel samples interpreted as int64; all in-range
// => really int64. (int32 data: each sample needs hi-word==0, P ~ 1e-145.)
// ---------------------------------------------------------------------------
__global__ void detect_idx_dtype_kernel(const long long* __restrict__ rows,
                                        int nelem, int N) {
    int t = threadIdx.x;
    int k = nelem / 4 < 32 ? nelem / 4 : 32;
    bool ok = true;
    if (t < k) {
        long long v = rows[t];
        ok = (v >= 0 && v < (long long)N);
    }
    unsigned m = __ballot_sync(0xffffffffu, ok);
    if (t == 0) g_idx_is_64 = (m == 0xffffffffu) ? 1 : 0;
}

__global__ void zero_int_kernel(int* __restrict__ p, int n) {
    int i = blockIdx.x * blockDim.x + threadIdx.x;
    if (i < n) p[i] = 0;
}

__global__ void zero_tail_kernel(float* __restrict__ out, int lo, int hi) {
    int i = lo + blockIdx.x * blockDim.x + threadIdx.x;
    if (i < hi) out[i] = 0.f;
}

// ---------------------------------------------------------------------------
// CSR build
// ---------------------------------------------------------------------------
__global__ __launch_bounds__(256)
void hist_kernel(const void* __restrict__ rows_raw, int E, int N,
                 int* __restrict__ deg) {
    int e = blockIdx.x * blockDim.x + threadIdx.x;
    if (e >= E) return;
    int r = g_idx_is_64 ? (int)__ldg((const long long*)rows_raw + e)
                        : __ldg((const int*)rows_raw + e);
    if ((unsigned)r < (unsigned)N) atomicAdd(&deg[r], 1);
}

__global__ __launch_bounds__(1024)
void scan1_kernel(const int* __restrict__ deg, int* __restrict__ rowptr,
                  int* __restrict__ bsum, int N) {
    __shared__ int s[1024];
    int t = threadIdx.x;
    int i = blockIdx.x * 1024 + t;
    int v = (i < N) ? deg[i] : 0;
    s[t] = v;
    __syncthreads();
    for (int off = 1; off < 1024; off <<= 1) {
        int u = (t >= off) ? s[t - off] : 0;
        __syncthreads();
        s[t] += u;
        __syncthreads();
    }
    if (i < N) rowptr[i] = s[t] - v;
    if (t == 1023) bsum[blockIdx.x] = s[1023];
}

__global__ __launch_bounds__(1024)
void scan2_kernel(int* __restrict__ bsum, int nb) {
    __shared__ int s[1024];
    int t = threadIdx.x;
    int v = (t < nb) ? bsum[t] : 0;
    s[t] = v;
    __syncthreads();
    for (int off = 1; off < 1024; off <<= 1) {
        int u = (t >= off) ? s[t - off] : 0;
        __syncthreads();
        s[t] += u;
        __syncthreads();
    }
    if (t < nb) bsum[t] = s[t] - v;
}

__global__ __launch_bounds__(1024)
void scan3_kernel(int* __restrict__ rowptr, int* __restrict__ cursor,
                  const int* __restrict__ bsum, int N, int E) {
    int i = blockIdx.x * 1024 + threadIdx.x;
    if (i < N) {
        int v = rowptr[i] + bsum[blockIdx.x];
        rowptr[i] = v;
        cursor[i] = v;
    }
    if (i == 0) rowptr[N] = E;
}

__global__ __launch_bounds__(256)
void scatter_kernel(const void* __restrict__ rows_raw,
                    const void* __restrict__ cols_raw,
                    const float* __restrict__ vals,
                    int* __restrict__ cursor,
                    int2* __restrict__ edges, int E, int N) {
    int e = blockIdx.x * blockDim.x + threadIdx.x;
    if (e >= E) return;
    int r, c;
    if (g_idx_is_64) {
        r = (int)__ldg((const long long*)rows_raw + e);
        c = (int)__ldg((const long long*)cols_raw + e);
    } else {
        r = __ldg((const int*)rows_raw + e);
        c = __ldg((const int*)cols_raw + e);
    }
    if ((unsigned)r >= (unsigned)N || (unsigned)c >= (unsigned)N) return;
    float v = __ldg(&vals[e]);
    int pos = atomicAdd(&cursor[r], 1);
    if (pos < NEDGES) edges[pos] = make_int2(c, __float_as_int(v));
}

// ---------------------------------------------------------------------------
// GEMM on tensor cores: h = x @ W + bias, tf32 mma.sync.m16n8k8.
// Block 128x64, 8 warps (4 in M, 2 in N), warp tile 32x32 (2x4 MMAs).
// Smem strides SA=36 / SB=72 make fragment LDS bank-conflict-free:
//   A frag bank = (4*gr + tc) mod 32  (all 32 lanes distinct)
//   B frag bank = (8*tc + gr) mod 32  (all 32 lanes distinct)
// tf32 rounding (cvt.rna) done once at smem-store time.
// ---------------------------------------------------------------------------
#define SA 36
#define SB 72

__device__ __forceinline__ uint32_t f32_to_tf32(float x) {
    uint32_t r;
    asm("cvt.rna.tf32.f32 %0, %1;" : "=r"(r) : "f"(x));
    return r;
}

__device__ __forceinline__ void mma_tf32(float c[4], const uint32_t a[4],
                                         const uint32_t b[2]) {
    asm volatile(
        "mma.sync.aligned.m16n8k8.row.col.f32.tf32.tf32.f32 "
        "{%0,%1,%2,%3}, {%4,%5,%6,%7}, {%8,%9}, {%0,%1,%2,%3};"
        : "+f"(c[0]), "+f"(c[1]), "+f"(c[2]), "+f"(c[3])
        : "r"(a[0]), "r"(a[1]), "r"(a[2]), "r"(a[3]), "r"(b[0]), "r"(b[1]));
}

__global__ __launch_bounds__(256)
void gemm_tf32_kernel(const float* __restrict__ X,
                      const float* __restrict__ W,
                      const float* __restrict__ bias,
                      float* __restrict__ H, int N) {
    __shared__ __align__(16) float As[128 * SA];   // 18432 B
    __shared__ __align__(16) float Bs[32 * SB];    //  9216 B

    const int tid  = threadIdx.x;
    const int warp = tid >> 5;
    const int lane = tid & 31;
    const int wm   = warp & 3;          // 0..3 -> M offset wm*32
    const int wn   = warp >> 2;         // 0..1 -> N offset wn*32
    const int gr   = lane >> 2;         // 0..7
    const int tc   = lane & 3;          // 0..3

    const int bm = blockIdx.x * 128;
    const int bn = blockIdx.y * 64;

    float c[2][4][4];
    #pragma unroll
    for (int mt = 0; mt < 2; mt++)
        #pragma unroll
        for (int nt = 0; nt < 4; nt++)
            #pragma unroll
            for (int i = 0; i < 4; i++) c[mt][nt][i] = 0.f;

    // global-load coordinates
    const int a_row0 = tid >> 3;          // 0..31 (4 iters stride 32)
    const int a_k4   = (tid & 7) * 4;     // 0..28
    const int b_k0   = tid >> 4;          // 0..15 (2 iters stride 16)
    const int b_n4   = (tid & 15) * 4;    // 0..60

    for (int k0 = 0; k0 < EDIM; k0 += 32) {
        // A tile: 128 rows x 32 k
        #pragma unroll
        for (int i = 0; i < 4; i++) {
            int row  = a_row0 + i * 32;
            int grow = bm + row;
            float4 v = make_float4(0.f, 0.f, 0.f, 0.f);
            if (grow < N)
                v = *(const float4*)(X + (size_t)grow * EDIM + k0 + a_k4);
            uint4 t;
            t.x = f32_to_tf32(v.x);  t.y = f32_to_tf32(v.y);
            t.z = f32_to_tf32(v.z);  t.w = f32_to_tf32(v.w);
            *(uint4*)&As[row * SA + a_k4] = t;
        }
        // B tile: 32 k x 64 n
        #pragma unroll
        for (int i = 0; i < 2; i++) {
            int k = b_k0 + i * 16;
            float4 v = *(const float4*)(W + (size_t)(k0 + k) * EDIM + bn + b_n4);
            uint4 t;
            t.x = f32_to_tf32(v.x);  t.y = f32_to_tf32(v.y);
            t.z = f32_to_tf32(v.z);  t.w = f32_to_tf32(v.w);
            *(uint4*)&Bs[k * SB + b_n4] = t;
        }
        __syncthreads();

        #pragma unroll
        for (int kk = 0; kk < 4; kk++) {
            uint32_t a[2][4], b[4][2];
            const uint32_t* Asu = (const uint32_t*)As;
            const uint32_t* Bsu = (const uint32_t*)Bs;
            #pragma unroll
            for (int mt = 0; mt < 2; mt++) {
                int r0 = (wm * 32 + mt * 16 + gr) * SA + kk * 8 + tc;
                a[mt][0] = Asu[r0];
                a[mt][1] = Asu[r0 + 8 * SA];
                a[mt][2] = Asu[r0 + 4];
                a[mt][3] = Asu[r0 + 8 * SA + 4];
            }
            #pragma unroll
            for (int nt = 0; nt < 4; nt++) {
                int r0 = (kk * 8 + tc) * SB + wn * 32 + nt * 8 + gr;
                b[nt][0] = Bsu[r0];
                b[nt][1] = Bsu[r0 + 4 * SB];
            }
            #pragma unroll
            for (int mt = 0; mt < 2; mt++)
                #pragma unroll
                for (int nt = 0; nt < 4; nt++)
                    mma_tf32(c[mt][nt], a[mt], b[nt]);
        }
        __syncthreads();
    }

    // epilogue: + bias, float2 stores
    #pragma unroll
    for (int nt = 0; nt < 4; nt++) {
        int bcol = bn + wn * 32 + nt * 8 + 2 * tc;
        float2 bv = *(const float2*)(bias + bcol);
        #pragma unroll
        for (int mt = 0; mt < 2; mt++) {
            int row = bm + wm * 32 + mt * 16 + gr;
            if (row < N) {
                float2 o = make_float2(c[mt][nt][0] + bv.x, c[mt][nt][1] + bv.y);
                *(float2*)(H + (size_t)row * EDIM + bcol) = o;
            }
            if (row + 8 < N) {
                float2 o = make_float2(c[mt][nt][2] + bv.x, c[mt][nt][3] + bv.y);
                *(float2*)(H + (size_t)(row + 8) * EDIM + bcol) = o;
            }
        }
    }
}

// ---------------------------------------------------------------------------
// SpMM over CSR: one warp per output row, register accumulation, no atomics.
// ---------------------------------------------------------------------------
__global__ __launch_bounds__(256)
void spmm_csr_kernel(const int* __restrict__ rowptr,
                     const int2* __restrict__ edges,
                     const float* __restrict__ H,
                     float* __restrict__ out, int N) {
    int warp = (blockIdx.x * blockDim.x + threadIdx.x) >> 5;
    int lane = threadIdx.x & 31;
    if (warp >= N) return;

    int s = __ldg(&rowptr[warp]);
    int e = __ldg(&rowptr[warp + 1]);

    float4 a0 = make_float4(0.f, 0.f, 0.f, 0.f);
    float4 a1 = make_float4(0.f, 0.f, 0.f, 0.f);

    #pragma unroll 4
    for (int i = s; i < e; i++) {
        int2  ev = __ldg(&edges[i]);
        float v  = __int_as_float(ev.y);
        const float4* hp = (const float4*)(H + (size_t)ev.x * EDIM);
        float4 x0 = __ldg(hp + lane);
        float4 x1 = __ldg(hp + lane + 32);
        a0.x += v * x0.x;  a0.y += v * x0.y;  a0.z += v * x0.z;  a0.w += v * x0.w;
        a1.x += v * x1.x;  a1.y += v * x1.y;  a1.z += v * x1.z;  a1.w += v * x1.w;
    }

    float4* op = (float4*)(out + (size_t)warp * EDIM);
    op[lane]      = a0;
    op[lane + 32] = a1;
}

// ---------------------------------------------------------------------------
// Launch. Inputs: x, G_rows, G_cols, G_vals, weight, bias.
// ---------------------------------------------------------------------------
extern "C" void kernel_launch(void* const* d_in, const int* in_sizes, int n_in,
                              void* d_out, int out_size) {
    const float* x     = (const float*)d_in[0];
    const void*  grows = d_in[1];
    const void*  gcols = d_in[2];
    const float* gvals = (const float*)d_in[3];
    const float* w     = (const float*)d_in[4];
    const float* bias  = (const float*)d_in[5];
    float*       out   = (float*)d_out;

    const int N = in_sizes[0] / EDIM;     // 100000
    const int E = in_sizes[1];            // 3200000

    float *d_h;    cudaGetSymbolAddress((void**)&d_h, g_h);
    int   *d_deg;  cudaGetSymbolAddress((void**)&d_deg, g_deg);
    int   *d_rp;   cudaGetSymbolAddress((void**)&d_rp, g_rowptr);
    int   *d_cur;  cudaGetSymbolAddress((void**)&d_cur, g_cursor);
    int   *d_bs;   cudaGetSymbolAddress((void**)&d_bs, g_bsum);
    int2  *d_edg;  cudaGetSymbolAddress((void**)&d_edg, g_edges);

    const int nb = (N + 1023) / 1024;

    detect_idx_dtype_kernel<<<1, 32>>>((const long long*)grows, E, N);
    zero_int_kernel<<<(N + 255) / 256, 256>>>(d_deg, N);
    {
        int lo = N * EDIM;
        if (out_size > lo)
            zero_tail_kernel<<<(out_size - lo + 255) / 256, 256>>>(out, lo, out_size);
    }

    // CSR build
    hist_kernel<<<(E + 255) / 256, 256>>>(grows, E, N, d_deg);
    scan1_kernel<<<nb, 1024>>>(d_deg, d_rp, d_bs, N);
    scan2_kernel<<<1, 1024>>>(d_bs, nb);
    scan3_kernel<<<nb, 1024>>>(d_rp, d_cur, d_bs, N, E);
    scatter_kernel<<<(E + 255) / 256, 256>>>(grows, gcols, gvals, d_cur, d_edg, E, N);

    // h = x @ W + bias  (tensor cores, tf32)
    {
        dim3 grid((N + 127) / 128, EDIM / 64);
        gemm_tf32_kernel<<<grid, 256>>>(x, w, bias, d_h, N);
    }

    // out = G @ h  (no atomics)
    {
        long long threads = (long long)N * 32;
        int blocks = (int)((threads + 255) / 256);
        spmm_csr_kernel<<<blocks, 256>>>(d_rp, d_edg, d_h, out, N);
    }
}